// round 14
// baseline (speedup 1.0000x reference)
#include <cuda_runtime.h>
#include <cuda_bf16.h>
#include <cstdint>
#include <math.h>

// Fixed problem shape (Qwen3VL vision attention, this dataset)
#define S_TOT 4096
#define E_DIM 1152
#define H_NUM 16
#define D_DIM 72
#define QKV_N (3 * E_DIM)          // 3456

// tcgen05 only legal in arch-specific (sm_103a) device pass.
#if !defined(__CUDA_ARCH__) || defined(__CUDA_ARCH_FEAT_SM103_ALL) || \
    defined(__CUDA_ARCH_SPECIFIC__) || defined(__CUDA_ARCH_FAMILY_SPECIFIC__)
#define TC_OK 1
#else
#define TC_OK 0
#endif

__device__ float g_qkv[(size_t)S_TOT * QKV_N];                 // [S, 3, H, D]

// bf16 hi/lo operand buffers
__device__ __nv_bfloat16 g_Ah[(size_t)S_TOT * E_DIM];          // A (hidden / attn out)
__device__ __nv_bfloat16 g_Al[(size_t)S_TOT * E_DIM];
__device__ __nv_bfloat16 g_Bh[(size_t)QKV_N * E_DIM];          // B (qkv_w)
__device__ __nv_bfloat16 g_Bl[(size_t)QKV_N * E_DIM];
__device__ __nv_bfloat16 g_Ph[(size_t)E_DIM * E_DIM];          // B (proj_w)
__device__ __nv_bfloat16 g_Pl[(size_t)E_DIM * E_DIM];

// pre-split attention operands
__device__ __nv_bfloat16 g_Qh[(size_t)S_TOT * E_DIM];          // [bh][m][72]
__device__ __nv_bfloat16 g_Ql[(size_t)S_TOT * E_DIM];
__device__ __nv_bfloat16 g_Kh[(size_t)S_TOT * E_DIM];
__device__ __nv_bfloat16 g_Kl[(size_t)S_TOT * E_DIM];
__device__ __nv_bfloat16 g_Vth[(size_t)S_TOT * E_DIM];         // [bh][d][L]
__device__ __nv_bfloat16 g_Vtl[(size_t)S_TOT * E_DIM];

// ---------------------------------------------------------------------------
// helpers
// ---------------------------------------------------------------------------
__device__ __forceinline__ uint32_t smem_to_u32(const void* p) {
    uint32_t a;
    asm("{ .reg .u64 t; cvta.to.shared.u64 t, %1; cvt.u32.u64 %0, t; }"
        : "=r"(a) : "l"(p));
    return a;
}

__device__ __forceinline__ uint32_t pack_bf16x2(__nv_bfloat16 a, __nv_bfloat16 b) {
    uint16_t ua = __bfloat16_as_ushort(a);
    uint16_t ub = __bfloat16_as_ushort(b);
    return (uint32_t)ua | ((uint32_t)ub << 16);
}

__device__ __forceinline__ void split2(float x, float y, uint32_t& hw, uint32_t& lw) {
    __nv_bfloat16 h0 = __float2bfloat16_rn(x);
    __nv_bfloat16 h1 = __float2bfloat16_rn(y);
    __nv_bfloat16 l0 = __float2bfloat16_rn(x - __bfloat162float(h0));
    __nv_bfloat16 l1 = __float2bfloat16_rn(y - __bfloat162float(h1));
    hw = pack_bf16x2(h0, h1);
    lw = pack_bf16x2(l0, l1);
}

__device__ __forceinline__ void split1(float x, __nv_bfloat16& h, __nv_bfloat16& l) {
    h = __float2bfloat16_rn(x);
    l = __float2bfloat16_rn(x - __bfloat162float(h));
}

#if TC_OK
__device__ __forceinline__ uint32_t elect_one_pred() {
    uint32_t pred;
    asm volatile("{\n\t.reg .pred p;\n\telect.sync _|p, 0xFFFFFFFF;\n\t"
                 "selp.b32 %0, 1, 0, p;\n\t}" : "=r"(pred));
    return pred;
}
#define MBARRIER_INIT(addr, cnt) \
    asm volatile("mbarrier.init.shared.b64 [%0], %1;" :: "r"((uint32_t)(addr)), "r"((uint32_t)(cnt)) : "memory")
#define MBARRIER_INVAL(addr) \
    asm volatile("mbarrier.inval.shared.b64 [%0];" :: "r"((uint32_t)(addr)) : "memory")
#define MBARRIER_WAIT_PARITY(mbar_smem_addr, phase_parity) do { \
    uint32_t _mbar = (uint32_t)(mbar_smem_addr); \
    uint32_t _parity = (uint32_t)(phase_parity); \
    uint32_t _done; \
    asm volatile("{\n\t.reg .pred p;\n\t" \
        "mbarrier.try_wait.parity.acquire.cta.shared::cta.b64 p, [%1], %2;\n\t" \
        "selp.b32 %0, 1, 0, p;\n\t}" \
        : "=r"(_done) : "r"(_mbar), "r"(_parity) : "memory"); \
    if (!_done) { \
        asm volatile("{\n\t.reg .pred P1;\n\t" \
            "WAIT_LOOP_%=:\n\t" \
            "mbarrier.try_wait.parity.acquire.cta.shared::cta.b64 P1, [%0], %1, 0x989680;\n\t" \
            "@P1 bra.uni WAIT_DONE_%=;\n\t" \
            "bra.uni WAIT_LOOP_%=;\n\t" \
            "WAIT_DONE_%=:\n\t}" \
            :: "r"(_mbar), "r"(_parity) : "memory"); \
    } \
} while(0)
#define TCGEN05_ALLOC(smem_result_addr, nCols) \
    asm volatile("tcgen05.alloc.cta_group::1.sync.aligned.shared::cta.b32 [%0], %1;" \
        :: "r"((uint32_t)(smem_result_addr)), "r"((uint32_t)(nCols)) : "memory")
#define TCGEN05_DEALLOC(tmem_addr, nCols) \
    asm volatile("tcgen05.dealloc.cta_group::1.sync.aligned.b32 %0, %1;" \
        :: "r"(tmem_addr), "r"((uint32_t)(nCols)))
#define TCGEN05_RELINQUISH() \
    asm volatile("tcgen05.relinquish_alloc_permit.cta_group::1.sync.aligned;")
#define TCGEN05_COMMIT(mbar_smem_addr) \
    asm volatile("tcgen05.commit.cta_group::1.mbarrier::arrive::one.shared::cluster.b64 [%0];" \
        :: "r"((uint32_t)(mbar_smem_addr)) : "memory")
#define TCGEN05_FENCE_BEFORE() \
    asm volatile("tcgen05.fence::before_thread_sync;" ::: "memory")
#define TCGEN05_FENCE_AFTER() \
    asm volatile("tcgen05.fence::after_thread_sync;" ::: "memory")
#define TCGEN05_WAIT_LD() \
    asm volatile("tcgen05.wait::ld.sync.aligned;" ::: "memory")
#define TCGEN05_WAIT_ST() \
    asm volatile("tcgen05.wait::st.sync.aligned;" ::: "memory")
#define TCGEN05_LD_32X32B_X32(r, tmem_addr) \
    asm volatile("tcgen05.ld.sync.aligned.32x32b.x32.b32 " \
        "{%0, %1, %2, %3, %4, %5, %6, %7, " \
        " %8, %9, %10, %11, %12, %13, %14, %15, " \
        " %16, %17, %18, %19, %20, %21, %22, %23, " \
        " %24, %25, %26, %27, %28, %29, %30, %31}, [%32];" \
        : "=r"((r)[0]),  "=r"((r)[1]),  "=r"((r)[2]),  "=r"((r)[3]), \
          "=r"((r)[4]),  "=r"((r)[5]),  "=r"((r)[6]),  "=r"((r)[7]), \
          "=r"((r)[8]),  "=r"((r)[9]),  "=r"((r)[10]), "=r"((r)[11]), \
          "=r"((r)[12]), "=r"((r)[13]), "=r"((r)[14]), "=r"((r)[15]), \
          "=r"((r)[16]), "=r"((r)[17]), "=r"((r)[18]), "=r"((r)[19]), \
          "=r"((r)[20]), "=r"((r)[21]), "=r"((r)[22]), "=r"((r)[23]), \
          "=r"((r)[24]), "=r"((r)[25]), "=r"((r)[26]), "=r"((r)[27]), \
          "=r"((r)[28]), "=r"((r)[29]), "=r"((r)[30]), "=r"((r)[31]) \
        : "r"(tmem_addr))
#define TCGEN05_LD_32X32B_X8(r, tmem_addr) \
    asm volatile("tcgen05.ld.sync.aligned.32x32b.x8.b32 " \
        "{%0, %1, %2, %3, %4, %5, %6, %7}, [%8];" \
        : "=r"((r)[0]), "=r"((r)[1]), "=r"((r)[2]), "=r"((r)[3]), \
          "=r"((r)[4]), "=r"((r)[5]), "=r"((r)[6]), "=r"((r)[7]) \
        : "r"(tmem_addr))
#define TCGEN05_ST_32X32B_X16(tmem_addr, r) \
    asm volatile("tcgen05.st.sync.aligned.32x32b.x16.b32 [%0], " \
        "{%1, %2, %3, %4, %5, %6, %7, %8, " \
        " %9, %10, %11, %12, %13, %14, %15, %16};" \
        :: "r"(tmem_addr), \
           "r"((r)[0]),  "r"((r)[1]),  "r"((r)[2]),  "r"((r)[3]), \
           "r"((r)[4]),  "r"((r)[5]),  "r"((r)[6]),  "r"((r)[7]), \
           "r"((r)[8]),  "r"((r)[9]),  "r"((r)[10]), "r"((r)[11]), \
           "r"((r)[12]), "r"((r)[13]), "r"((r)[14]), "r"((r)[15]) \
        : "memory")

static constexpr uint64_t SMEM_DESC_BASE_SW128 =
    (uint64_t(2)  << 61) | (uint64_t(1) << 46) | (uint64_t(64) << 32) | (uint64_t(1) << 16);
#define MAKE_SMEM_DESC(base_addr) \
    (SMEM_DESC_BASE_SW128 | ((uint64_t)((base_addr) >> 4) & 0x3FFF))

__device__ __forceinline__ void mma_bf16_ss(uint32_t d, uint64_t ad, uint64_t bd,
                                            uint32_t idesc, uint32_t enable) {
    asm volatile(
        "{\n\t.reg .pred p;\n\tsetp.ne.u32 p, %4, 0;\n\t"
        "tcgen05.mma.cta_group::1.kind::f16 [%0], %1, %2, %3, {%5, %5, %5, %5}, p;\n\t}"
        :: "r"(d), "l"(ad), "l"(bd), "r"(idesc), "r"(enable), "r"(0u)
        : "memory");
}
__device__ __forceinline__ void mma_bf16_ts(uint32_t d, uint32_t a, uint64_t bd,
                                            uint32_t idesc, uint32_t enable) {
    asm volatile(
        "{\n\t.reg .pred p;\n\tsetp.ne.u32 p, %4, 0;\n\t"
        "tcgen05.mma.cta_group::1.kind::f16 [%0], [%1], %2, %3, {%5, %5, %5, %5}, p;\n\t}"
        :: "r"(d), "r"(a), "l"(bd), "r"(idesc), "r"(enable), "r"(0u)
        : "memory");
}

__device__ __forceinline__ uint32_t kmaj_off(int row, int col, int natr) {
    int ac = col >> 6, ic = col & 63;
    int ar = row >> 3, ir = row & 7;
    uint32_t off = (uint32_t)((ar + ac * natr) * 1024 + ir * 128 + ic * 2);
    return off ^ ((off >> 3) & 0x70);
}
#endif // TC_OK

// ---------------------------------------------------------------------------
// one-shot fp32 -> bf16 hi/lo split for hidden, qkv_w, proj_w
// ---------------------------------------------------------------------------
__global__ __launch_bounds__(256) void split_all_kernel(
    const float* __restrict__ hidden, const float* __restrict__ qkv_w,
    const float* __restrict__ proj_w)
{
    const int nA4 = (S_TOT * E_DIM) / 4;
    const int nB4 = (QKV_N * E_DIM) / 4;
    const int nP4 = (E_DIM * E_DIM) / 4;
    int i4 = blockIdx.x * blockDim.x + threadIdx.x;
    const float* src;
    __nv_bfloat16 *hi, *lo;
    size_t o4;
    if (i4 < nA4) {
        src = hidden; hi = g_Ah; lo = g_Al; o4 = i4;
    } else if (i4 < nA4 + nB4) {
        src = qkv_w; hi = g_Bh; lo = g_Bl; o4 = i4 - nA4;
    } else if (i4 < nA4 + nB4 + nP4) {
        src = proj_w; hi = g_Ph; lo = g_Pl; o4 = i4 - nA4 - nB4;
    } else return;
    float4 v = *(const float4*)(src + o4 * 4);
    uint32_t h01, l01, h23, l23;
    split2(v.x, v.y, h01, l01);
    split2(v.z, v.w, h23, l23);
    *(uint2*)(hi + o4 * 4) = make_uint2(h01, h23);
    *(uint2*)(lo + o4 * 4) = make_uint2(l01, l23);
}

// ---------------------------------------------------------------------------
// tcgen05 GEMM: 256x128 tile, cp.async, KC=64, SINGLE stage buffer ->
// 97KB smem/CTA -> occupancy 2 (two CTAs per SM overlap copy and MMA
// phases; TMEM 256+256 = 512 fits the pool). bsel: 0=g_B*, 1=g_P*
// ---------------------------------------------------------------------------
#define KC 64
#define TILE_B 16384
#define STAGE_B (6 * TILE_B)              // 96KB
#define GEMM_SMEM (1024 + STAGE_B)        // 99328 <= 113664 -> occ 2

#if TC_OK
__device__ __forceinline__ void cp_tile(uint32_t sdst,
                                        const __nv_bfloat16* __restrict__ gsrc,
                                        int row0, int k0, int K, int tid) {
    #pragma unroll
    for (int it = 0; it < 4; it++) {
        int idx = tid + it * 256;
        int rr = idx >> 3, c = idx & 7;
        const void* src = gsrc + (size_t)(row0 + rr) * K + k0 + c * 8;
        uint32_t off = (uint32_t)((rr << 7) | (c << 4));
        uint32_t sw = off ^ ((off >> 3) & 0x70);
        asm volatile("cp.async.cg.shared.global [%0], [%1], 16;"
            :: "r"(sdst + sw), "l"(src) : "memory");
    }
}
__device__ __forceinline__ void cp_stage(uint32_t base, int row0, int col0,
                                         int k0, int K, int tid,
                                         const __nv_bfloat16* Bh,
                                         const __nv_bfloat16* Bl) {
    cp_tile(base,              g_Ah, row0,       k0, K, tid);
    cp_tile(base + TILE_B,     g_Al, row0,       k0, K, tid);
    cp_tile(base + 2 * TILE_B, g_Ah, row0 + 128, k0, K, tid);
    cp_tile(base + 3 * TILE_B, g_Al, row0 + 128, k0, K, tid);
    cp_tile(base + 4 * TILE_B, Bh,   col0,       k0, K, tid);
    cp_tile(base + 5 * TILE_B, Bl,   col0,       k0, K, tid);
    asm volatile("cp.async.commit_group;" ::: "memory");
}
__device__ __forceinline__ void issue_chunk2(uint32_t base, uint32_t tmem,
                                             uint32_t idesc, uint32_t mbar, int first) {
    asm volatile("fence.proxy.async.shared::cta;" ::: "memory");
    uint64_t dAh0 = MAKE_SMEM_DESC(base);
    uint64_t dAl0 = MAKE_SMEM_DESC(base + TILE_B);
    uint64_t dAh1 = MAKE_SMEM_DESC(base + 2 * TILE_B);
    uint64_t dAl1 = MAKE_SMEM_DESC(base + 3 * TILE_B);
    uint64_t dBh  = MAKE_SMEM_DESC(base + 4 * TILE_B);
    uint64_t dBl  = MAKE_SMEM_DESC(base + 5 * TILE_B);
    #pragma unroll
    for (int ks = 0; ks < 4; ks++) {
        uint32_t en = (first && ks == 0) ? 0u : 1u;
        mma_bf16_ss(tmem,       dAh0 + ks * 2, dBh + ks * 2, idesc, en);
        mma_bf16_ss(tmem,       dAh0 + ks * 2, dBl + ks * 2, idesc, 1u);
        mma_bf16_ss(tmem,       dAl0 + ks * 2, dBh + ks * 2, idesc, 1u);
        mma_bf16_ss(tmem + 128, dAh1 + ks * 2, dBh + ks * 2, idesc, en);
        mma_bf16_ss(tmem + 128, dAh1 + ks * 2, dBl + ks * 2, idesc, 1u);
        mma_bf16_ss(tmem + 128, dAl1 + ks * 2, dBh + ks * 2, idesc, 1u);
    }
    TCGEN05_COMMIT(mbar);
}
#endif

__global__ __launch_bounds__(256, 2) void gemm_tc(
    const float* __restrict__ bias, float* __restrict__ Cext,
    int M, int N, int K, int mode, int bsel)
{
    extern __shared__ char smem[];
    const int tid = threadIdx.x;
    float* C = mode ? Cext : g_qkv;
    const __nv_bfloat16* Bh = bsel ? g_Ph : g_Bh;
    const __nv_bfloat16* Bl = bsel ? g_Pl : g_Bl;

#if TC_OK
    uint32_t sb = smem_to_u32(smem);
    const int wid = tid >> 5;

    if (wid == 0) {
        TCGEN05_ALLOC(sb, 256);
        TCGEN05_RELINQUISH();
    }
    if (tid == 0) {
        MBARRIER_INIT(sb + 8, 1);
    }
    __syncthreads();
    uint32_t tmem;
    asm volatile("ld.shared.b32 %0, [%1];" : "=r"(tmem) : "r"(sb));

    const int row0 = blockIdx.y * 256;
    const int col0 = blockIdx.x * 128;
    const int NC = K / KC;
    const uint32_t idesc = 0x490u | ((128u / 8) << 17) | ((128u / 16) << 24);
    const uint32_t base = sb + 1024;

    int ph = 0;
    for (int c = 0; c < NC; c++) {
        cp_stage(base, row0, col0, c * KC, K, tid, Bh, Bl);
        asm volatile("cp.async.wait_group 0;" ::: "memory");
        __syncthreads();
        if (tid < 32 && elect_one_pred())
            issue_chunk2(base, tmem, idesc, sb + 8, c == 0);
        // wait MMA before overwriting the single stage buffer
        MBARRIER_WAIT_PARITY(sb + 8, ph);
        ph ^= 1;
    }
    TCGEN05_FENCE_AFTER();

    {
        const int lane = tid & 31;
        const int sub = wid & 3;
        const int grp = wid >> 2;
        const int r = row0 + grp * 128 + sub * 32 + lane;
        const uint32_t tm = tmem + grp * 128;
        #pragma unroll
        for (int cc = 0; cc < 4; cc++) {
            uint32_t regs[32];
            TCGEN05_LD_32X32B_X32(regs, tm + cc * 32);
            TCGEN05_WAIT_LD();
            float* crow = C + (size_t)r * N + col0 + cc * 32;
            const float* brow = bias + col0 + cc * 32;
            #pragma unroll
            for (int j = 0; j < 32; j += 4) {
                float4 o;
                o.x = __uint_as_float(regs[j + 0]) + brow[j + 0];
                o.y = __uint_as_float(regs[j + 1]) + brow[j + 1];
                o.z = __uint_as_float(regs[j + 2]) + brow[j + 2];
                o.w = __uint_as_float(regs[j + 3]) + brow[j + 3];
                *(float4*)(crow + j) = o;
            }
        }
    }

    __syncthreads();
    if (tid == 0) { MBARRIER_INVAL(sb + 8); }
    __syncthreads();
    if (wid == 0) TCGEN05_DEALLOC(tmem, 256);

#else
    // fallback: fp32 FFMA tiled GEMM (compile-only for family-PTX pass)
    float* As = (float*)smem;
    float* Bs = (float*)(smem + 8 * 128 * 4);
    const int col0 = blockIdx.x * 128;
    const int lr = tid >> 1;
    const int lc = (tid & 1) * 4;
    const int tx = tid & 15;
    const int ty = tid >> 4;
    for (int half = 0; half < 2; half++) {
        const int row0 = blockIdx.y * 256 + half * 128;
        float acc[8][8];
        for (int i = 0; i < 8; i++) for (int j = 0; j < 8; j++) acc[i][j] = 0.f;
        for (int k0 = 0; k0 < K; k0 += 8) {
            for (int u = 0; u < 4; u++) {
                size_t ai = (size_t)(row0 + lr) * K + k0 + lc + u;
                size_t bi = (size_t)(col0 + lr) * K + k0 + lc + u;
                As[(lc + u) * 128 + lr] = __bfloat162float(g_Ah[ai]) + __bfloat162float(g_Al[ai]);
                Bs[(lc + u) * 128 + lr] = __bfloat162float(Bh[bi]) + __bfloat162float(Bl[bi]);
            }
            __syncthreads();
            for (int k = 0; k < 8; k++)
                for (int i = 0; i < 8; i++)
                    for (int j = 0; j < 8; j++)
                        acc[i][j] = fmaf(As[k * 128 + ty * 8 + i], Bs[k * 128 + tx * 8 + j], acc[i][j]);
            __syncthreads();
        }
        for (int i = 0; i < 8; i++) {
            size_t r = (size_t)(row0 + ty * 8 + i);
            for (int j = 0; j < 8; j++) {
                int cidx = col0 + tx * 8 + j;
                C[r * N + cidx] = acc[i][j] + bias[cidx];
            }
        }
        __syncthreads();
    }
#endif
}

// ---------------------------------------------------------------------------
// merged RoPE + V-transpose kernel.
// ---------------------------------------------------------------------------
#define ROPE_BLOCKS ((S_TOT * H_NUM * 36) / 256)    // 9216

__global__ __launch_bounds__(256) void ropevt_kernel(
    const float* __restrict__ cosv, const float* __restrict__ sinv, int L)
{
    __shared__ float vs[64][73];
    const int tid = threadIdx.x;

    if (blockIdx.x < ROPE_BLOCKS) {
        const float SCALE = 0.11785113019775793f;
        int idx = blockIdx.x * 256 + tid;
        int d = idx % 36;
        int h = (idx / 36) % H_NUM;
        int s = idx / (36 * H_NUM);

        float c1 = cosv[s * D_DIM + d],      s1 = sinv[s * D_DIM + d];
        float c2 = cosv[s * D_DIM + d + 36], s2 = sinv[s * D_DIM + d + 36];

        int b = s / L, m = s - b * L;
        size_t obase = ((size_t)(b * H_NUM + h) * L + m) * 72;

        size_t base = (size_t)s * QKV_N + h * D_DIM;
        float x1 = g_qkv[base + d], x2 = g_qkv[base + d + 36];
        float q1 = (x1 * c1 - x2 * s1) * SCALE;
        float q2 = (x2 * c2 + x1 * s2) * SCALE;
        __nv_bfloat16 hh, ll;
        split1(q1, hh, ll); g_Qh[obase + d] = hh;      g_Ql[obase + d] = ll;
        split1(q2, hh, ll); g_Qh[obase + d + 36] = hh; g_Ql[obase + d + 36] = ll;

        base += E_DIM;
        x1 = g_qkv[base + d]; x2 = g_qkv[base + d + 36];
        float k1 = x1 * c1 - x2 * s1;
        float k2 = x2 * c2 + x1 * s2;
        split1(k1, hh, ll); g_Kh[obase + d] = hh;      g_Kl[obase + d] = ll;
        split1(k2, hh, ll); g_Kh[obase + d + 36] = hh; g_Kl[obase + d + 36] = ll;
    } else {
        int bid = blockIdx.x - ROPE_BLOCKS;
        const int ntk = L / 64;
        const int bh = bid / ntk;
        const int k0 = (bid - bh * ntk) * 64;
        const int b = bh / H_NUM, h = bh % H_NUM;

        for (int idx = tid; idx < 64 * 72; idx += 256) {
            int r = idx / 72, d = idx % 72;
            vs[r][d] = g_qkv[(size_t)(b * L + k0 + r) * QKV_N + 2 * E_DIM + h * D_DIM + d];
        }
        __syncthreads();
        for (int idx = tid; idx < 72 * 32; idx += 256) {
            int d = idx >> 5, k2 = (idx & 31) * 2;
            uint32_t hw, lw;
            split2(vs[k2][d], vs[k2 + 1][d], hw, lw);
            size_t o = ((size_t)bh * 72 + d) * L + k0 + k2;
            *(uint32_t*)&g_Vth[o] = hw;
            *(uint32_t*)&g_Vtl[o] = lw;
        }
    }
}

// ---------------------------------------------------------------------------
// Fused flash attention v7 (unchanged from R13; best-measured variant).
// SMEM: ctrl 0..63 | rowsum[4][128] 64..2112 | QH 4096 | QL 36864 |
//       KH 69632 | KL 102400 | V0H 135168 | V0L 153600 | V1H 172032 |
//       V1L 190464 | end 208896
// TMEM: O 0..71 | S0 128..255 | S1 256..383 | Ph 384..447 | Pl 448..511
// ---------------------------------------------------------------------------
#define AT7_QH 4096
#define AT7_QL 36864
#define AT7_KH 69632
#define AT7_KL 102400
#define AT7_V0H 135168
#define AT7_V0L 153600
#define AT7_V1H 172032
#define AT7_V1L 190464
#define AT7_SMEM 208896

#if TC_OK
__device__ __forceinline__ void cp_att_k(uint32_t sdst,
    const __nv_bfloat16* __restrict__ g, int bh, int k0, int L, int tid)
{
    #pragma unroll
    for (int it = 0; it < 3; it++) {
        int idx = tid + it * 512;
        if (idx < 1152) {
            int r = idx / 9, c = idx - r * 9;
            const void* src = g + ((size_t)bh * L + k0 + r) * 72 + c * 8;
            uint32_t off = kmaj_off(r, c * 8, 16);
            asm volatile("cp.async.cg.shared.global [%0], [%1], 16;"
                :: "r"(sdst + off), "l"(src) : "memory");
        }
    }
}
__device__ __forceinline__ void cp_att_v(uint32_t sdst,
    const __nv_bfloat16* __restrict__ g, int bh, int k0, int L, int tid)
{
    #pragma unroll
    for (int it = 0; it < 3; it++) {
        int idx = tid + it * 512;
        if (idx < 1152) {
            int d = idx >> 4, c = idx & 15;
            const void* src = g + ((size_t)bh * 72 + d) * L + k0 + c * 8;
            uint32_t off = kmaj_off(d, c * 8, 9);
            asm volatile("cp.async.cg.shared.global [%0], [%1], 16;"
                :: "r"(sdst + off), "l"(src) : "memory");
        }
    }
}
__device__ __forceinline__ void issue_s(uint32_t tmem_S, uint32_t sb,
                                        uint32_t idesc_s, uint32_t mbar) {
    const int qk_off[5] = {0, 2, 4, 6, 1024};
    uint64_t dQH = MAKE_SMEM_DESC(sb + AT7_QH);
    uint64_t dQL = MAKE_SMEM_DESC(sb + AT7_QL);
    uint64_t dKH = MAKE_SMEM_DESC(sb + AT7_KH);
    uint64_t dKL = MAKE_SMEM_DESC(sb + AT7_KL);
    #pragma unroll
    for (int ks = 0; ks < 5; ks++) {
        mma_bf16_ss(tmem_S, dQH + qk_off[ks], dKH + qk_off[ks], idesc_s, ks > 0);
        mma_bf16_ss(tmem_S, dQH + qk_off[ks], dKL + qk_off[ks], idesc_s, 1u);
        mma_bf16_ss(tmem_S, dQL + qk_off[ks], dKH + qk_off[ks], idesc_s, 1u);
    }
    TCGEN05_COMMIT(mbar);
}
__device__ __forceinline__ void issue_pv(uint32_t tmem_O, uint32_t tmem_Ph,
                                         uint32_t tmem_Pl, uint32_t vbase,
                                         uint32_t idesc_o, uint32_t mbar, int first) {
    const int v_off[8] = {0, 2, 4, 6, 576, 578, 580, 582};
    uint64_t dVH = MAKE_SMEM_DESC(vbase);
    uint64_t dVL = MAKE_SMEM_DESC(vbase + (AT7_V0L - AT7_V0H));
    #pragma unroll
    for (int ks = 0; ks < 8; ks++) {
        mma_bf16_ts(tmem_O, tmem_Ph + ks * 8, dVH + v_off[ks], idesc_o,
                    (first && ks == 0) ? 0u : 1u);
        mma_bf16_ts(tmem_O, tmem_Ph + ks * 8, dVL + v_off[ks], idesc_o, 1u);
        mma_bf16_ts(tmem_O, tmem_Pl + ks * 8, dVH + v_off[ks], idesc_o, 1u);
    }
    TCGEN05_COMMIT(mbar);
}
#endif

__global__ __launch_bounds__(512, 1) void fused_attn_kernel(int L)
{
    extern __shared__ char smem[];
    const int tid = threadIdx.x;
    const int bh = blockIdx.y;
    const int m0 = blockIdx.x * 128;
    const int nkt = L / 128;

#if TC_OK
    uint32_t sb = smem_to_u32(smem);
    const int wid = tid >> 5;
    const int lane = tid & 31;

    if (wid == 0) {
        TCGEN05_ALLOC(sb, 512);
        TCGEN05_RELINQUISH();
    }
    if (tid == 0) {
        MBARRIER_INIT(sb + 8, 1);    // mb_s  (S MMA completion)
        MBARRIER_INIT(sb + 16, 1);   // mb_pv (PV MMA completion)
    }
    __syncthreads();
    uint32_t tmem;
    asm volatile("ld.shared.b32 %0, [%1];" : "=r"(tmem) : "r"(sb));
    const uint32_t tmem_O  = tmem;
    const uint32_t tmem_Ph = tmem + 384;
    const uint32_t tmem_Pl = tmem + 448;

    const uint32_t idesc_s = 0x490u | (16u << 17) | (8u << 24);  // N=128
    const uint32_t idesc_o = 0x490u | (9u  << 17) | (8u << 24);  // N=72

    // prologue: load Q + K(0) (group A), V(0) (group B)
    cp_att_k(sb + AT7_QH, g_Qh, bh, m0, L, tid);
    cp_att_k(sb + AT7_QL, g_Ql, bh, m0, L, tid);
    cp_att_k(sb + AT7_KH, g_Kh, bh, 0, L, tid);
    cp_att_k(sb + AT7_KL, g_Kl, bh, 0, L, tid);
    asm volatile("cp.async.commit_group;" ::: "memory");
    cp_att_v(sb + AT7_V0H, g_Vth, bh, 0, L, tid);
    cp_att_v(sb + AT7_V0L, g_Vtl, bh, 0, L, tid);
    asm volatile("cp.async.commit_group;" ::: "memory");

    // zero pad cols 72..79 of QH, QL, KH, KL
    {
        int bf = tid >> 7, r = tid & 127;
        uint32_t bases[4] = {AT7_QH, AT7_QL, AT7_KH, AT7_KL};
        uint32_t dst = sb + bases[bf] + kmaj_off(r, 72, 16);
        asm volatile("st.shared.v4.b32 [%0], {%1,%1,%1,%1};"
            :: "r"(dst), "r"(0u) : "memory");
    }

    // Q + K(0) ready -> issue S(0)
    asm volatile("cp.async.wait_group 1;" ::: "memory");
    __syncthreads();
    if (tid < 32 && elect_one_pred()) {
        asm volatile("fence.proxy.async.shared::cta;" ::: "memory");
        TCGEN05_FENCE_AFTER();
        issue_s(tmem + 128, sb, idesc_s, sb + 8);
    }
    MBARRIER_WAIT_PARITY(sb + 8, 0);
    int ph_s = 1;
    if (nkt > 1) {
        cp_att_k(sb + AT7_KH, g_Kh, bh, 128, L, tid);
        cp_att_k(sb + AT7_KL, g_Kl, bh, 128, L, tid);
        asm volatile("cp.async.commit_group;" ::: "memory");
    }

    const int sub = wid & 3;
    const int grp = wid >> 2;
    const int row = sub * 32 + lane;
    const int c0 = grp * 32;
    const uint32_t woff = (uint32_t)sub << 21;
    float psum = 0.f;
    int ph_pv = 0;

    for (int kt = 0; kt < nkt; kt++) {
        const uint32_t tmem_S = tmem + 128 + (kt & 1) * 128;

        asm volatile("cp.async.wait_group 0;" ::: "memory");
        __syncthreads();
        if (kt + 1 < nkt) {
            if (tid < 32 && elect_one_pred()) {
                asm volatile("fence.proxy.async.shared::cta;" ::: "memory");
                TCGEN05_FENCE_AFTER();
                issue_s(tmem + 128 + ((kt + 1) & 1) * 128, sb, idesc_s, sb + 8);
            }
        }
        TCGEN05_FENCE_AFTER();

        uint32_t r32[32];
        TCGEN05_LD_32X32B_X32(r32, tmem_S + c0);
        TCGEN05_WAIT_LD();
        uint32_t ph16[16], pl16[16];
        #pragma unroll
        for (int j = 0; j < 16; j++) {
            float e0 = __expf(__uint_as_float(r32[2 * j]));
            float e1 = __expf(__uint_as_float(r32[2 * j + 1]));
            psum += e0 + e1;
            split2(e0, e1, ph16[j], pl16[j]);
        }

        if (kt >= 1) {
            MBARRIER_WAIT_PARITY(sb + 16, ph_pv);
            ph_pv ^= 1;
        }
        TCGEN05_FENCE_AFTER();

        TCGEN05_ST_32X32B_X16(tmem_Ph + grp * 16 + woff, ph16);
        TCGEN05_ST_32X32B_X16(tmem_Pl + grp * 16 + woff, pl16);
        TCGEN05_WAIT_ST();
        TCGEN05_FENCE_BEFORE();

        if (kt + 1 < nkt) {
            MBARRIER_WAIT_PARITY(sb + 8, ph_s);
            ph_s ^= 1;
            if (kt + 2 < nkt) {
                cp_att_k(sb + AT7_KH, g_Kh, bh, (kt + 2) * 128, L, tid);
                cp_att_k(sb + AT7_KL, g_Kl, bh, (kt + 2) * 128, L, tid);
            }
            uint32_t vb = sb + ((kt + 1) & 1 ? AT7_V1H : AT7_V0H);
            cp_att_v(vb,                       g_Vth, bh, (kt + 1) * 128, L, tid);
            cp_att_v(vb + (AT7_V0L - AT7_V0H), g_Vtl, bh, (kt + 1) * 128, L, tid);
            asm volatile("cp.async.commit_group;" ::: "memory");
        }
        __syncthreads();

        if (tid < 32 && elect_one_pred()) {
            asm volatile("fence.proxy.async.shared::cta;" ::: "memory");
            TCGEN05_FENCE_AFTER();
            uint32_t vbase = sb + ((kt & 1) ? AT7_V1H : AT7_V0H);
            issue_pv(tmem_O, tmem_Ph, tmem_Pl, vbase, idesc_o, sb + 16, kt == 0);
        }
    }

    MBARRIER_WAIT_PARITY(sb + 16, ph_pv);
    TCGEN05_FENCE_AFTER();

    *(float*)(smem + 64 + (grp * 128 + row) * 4) = psum;
    __syncthreads();

    if (wid < 4) {
        float rs = *(float*)(smem + 64 + row * 4) +
                   *(float*)(smem + 64 + (128 + row) * 4) +
                   *(float*)(smem + 64 + (256 + row) * 4) +
                   *(float*)(smem + 64 + (384 + row) * 4);
        float inv = 1.f / rs;
        uint32_t r32[72];
        TCGEN05_LD_32X32B_X32(r32,      tmem_O);
        TCGEN05_LD_32X32B_X32(r32 + 32, tmem_O + 32);
        TCGEN05_LD_32X32B_X8 (r32 + 64, tmem_O + 64);
        TCGEN05_WAIT_LD();
        const int b = bh / H_NUM, h = bh % H_NUM;
        size_t obase = (size_t)(b * L + m0 + row) * E_DIM + h * D_DIM;
        #pragma unroll
        for (int j = 0; j < 72; j += 2) {
            float o0 = __uint_as_float(r32[j]) * inv;
            float o1 = __uint_as_float(r32[j + 1]) * inv;
            uint32_t hw, lw;
            split2(o0, o1, hw, lw);
            *(uint32_t*)&g_Ah[obase + j] = hw;
            *(uint32_t*)&g_Al[obase + j] = lw;
        }
    }

    __syncthreads();
    if (tid == 0) {
        MBARRIER_INVAL(sb + 8);
        MBARRIER_INVAL(sb + 16);
    }
    __syncthreads();
    if (wid == 0) TCGEN05_DEALLOC(tmem, 512);

#else
    // naive fallback (compile-only for the family-PTX pass); reads split Q/K
    const int b = bh / H_NUM, h = bh % H_NUM;
    const int row = tid >> 2;
    const int hf = tid & 3;
    if (row < 128 && hf < 2) {
        float q[D_DIM];
        size_t qbase = ((size_t)bh * L + m0 + row) * 72;
        for (int d = 0; d < D_DIM; d++)
            q[d] = __bfloat162float(g_Qh[qbase + d]) + __bfloat162float(g_Ql[qbase + d]);
        float o[36];
        for (int j = 0; j < 36; j++) o[j] = 0.f;
        float rsum = 0.f;
        for (int k = 0; k < L; k++) {
            size_t kbase = ((size_t)bh * L + k) * 72;
            float s = 0.f;
            for (int d = 0; d < D_DIM; d++)
                s += q[d] * (__bfloat162float(g_Kh[kbase + d]) + __bfloat162float(g_Kl[kbase + d]));
            float e = __expf(s);
            rsum += e;
            const float* vv = &g_qkv[(size_t)(b * L + k) * QKV_N + 2 * E_DIM + h * D_DIM + hf * 36];
            for (int j = 0; j < 36; j++) o[j] += e * vv[j];
        }
        float inv = 1.f / rsum;
        size_t obase = (size_t)(b * L + m0 + row) * E_DIM + h * D_DIM + hf * 36;
        for (int j = 0; j < 36; j++) {
            float val = o[j] * inv;
            __nv_bfloat16 hi = __float2bfloat16_rn(val);
            __nv_bfloat16 lo = __float2bfloat16_rn(val - __bfloat162float(hi));
            g_Ah[obase + j] = hi;
            g_Al[obase + j] = lo;
        }
    }
#endif
}

// ---------------------------------------------------------------------------
extern "C" void kernel_launch(void* const* d_in, const int* in_sizes, int n_in,
                              void* d_out, int out_size)
{
    const float* hidden = (const float*)d_in[0];
    const float* cosv   = (const float*)d_in[1];
    const float* sinv   = (const float*)d_in[2];
    const float* qkv_w  = (const float*)d_in[3];
    const float* qkv_b  = (const float*)d_in[4];
    const float* proj_w = (const float*)d_in[5];
    const float* proj_b = (const float*)d_in[6];

    const int S = S_TOT;
    const int n_chunks = in_sizes[7] - 1;
    const int L = S / n_chunks;
    const int nbh = n_chunks * H_NUM;

    cudaFuncSetAttribute(gemm_tc,
        cudaFuncAttributeMaxDynamicSharedMemorySize, GEMM_SMEM);
    cudaFuncSetAttribute(fused_attn_kernel,
        cudaFuncAttributeMaxDynamicSharedMemorySize, AT7_SMEM);

    // 1) split hidden + qkv_w + proj_w (one launch)
    {
        int total4 = (S * E_DIM + QKV_N * E_DIM + E_DIM * E_DIM) / 4;
        split_all_kernel<<<(total4 + 255) / 256, 256>>>(hidden, qkv_w, proj_w);
    }

    // 2) QKV GEMM (occupancy-2, single-stage)
    gemm_tc<<<dim3(QKV_N / 128, S / 256), 256, GEMM_SMEM>>>(
        qkv_b, nullptr, S, QKV_N, E_DIM, 0, 0);

    // 3) RoPE + V transpose (one launch)
    ropevt_kernel<<<ROPE_BLOCKS + nbh * (L / 64), 256>>>(cosv, sinv, L);

    // 4) fused attention v7 -> g_Ah/g_Al
    fused_attn_kernel<<<dim3(L / 128, nbh), 512, AT7_SMEM>>>(L);

    // 5) proj GEMM
    gemm_tc<<<dim3(E_DIM / 128, S / 256), 256, GEMM_SMEM>>>(
        proj_b, (float*)d_out, S, E_DIM, E_DIM, 1, 1);
}

// round 15
// speedup vs baseline: 1.0745x; 1.0745x over previous
#include <cuda_runtime.h>
#include <cuda_bf16.h>
#include <cstdint>
#include <math.h>

// Fixed problem shape (Qwen3VL vision attention, this dataset)
#define S_TOT 4096
#define E_DIM 1152
#define H_NUM 16
#define D_DIM 72
#define QKV_N (3 * E_DIM)          // 3456

// tcgen05 only legal in arch-specific (sm_103a) device pass.
#if !defined(__CUDA_ARCH__) || defined(__CUDA_ARCH_FEAT_SM103_ALL) || \
    defined(__CUDA_ARCH_SPECIFIC__) || defined(__CUDA_ARCH_FAMILY_SPECIFIC__)
#define TC_OK 1
#else
#define TC_OK 0
#endif

__device__ float g_qkv[(size_t)S_TOT * QKV_N];                 // [S, 3, H, D]

// bf16 hi/lo operand buffers
__device__ __nv_bfloat16 g_Ah[(size_t)S_TOT * E_DIM];          // A (hidden / attn out)
__device__ __nv_bfloat16 g_Al[(size_t)S_TOT * E_DIM];
__device__ __nv_bfloat16 g_Bh[(size_t)QKV_N * E_DIM];          // B (qkv_w)
__device__ __nv_bfloat16 g_Bl[(size_t)QKV_N * E_DIM];
__device__ __nv_bfloat16 g_Ph[(size_t)E_DIM * E_DIM];          // B (proj_w)
__device__ __nv_bfloat16 g_Pl[(size_t)E_DIM * E_DIM];

// pre-split attention operands
__device__ __nv_bfloat16 g_Qh[(size_t)S_TOT * E_DIM];          // [bh][m][72]
__device__ __nv_bfloat16 g_Ql[(size_t)S_TOT * E_DIM];
__device__ __nv_bfloat16 g_Kh[(size_t)S_TOT * E_DIM];
__device__ __nv_bfloat16 g_Kl[(size_t)S_TOT * E_DIM];
__device__ __nv_bfloat16 g_Vth[(size_t)S_TOT * E_DIM];         // [bh][d][L]
__device__ __nv_bfloat16 g_Vtl[(size_t)S_TOT * E_DIM];

// ---------------------------------------------------------------------------
// helpers
// ---------------------------------------------------------------------------
__device__ __forceinline__ uint32_t smem_to_u32(const void* p) {
    uint32_t a;
    asm("{ .reg .u64 t; cvta.to.shared.u64 t, %1; cvt.u32.u64 %0, t; }"
        : "=r"(a) : "l"(p));
    return a;
}

__device__ __forceinline__ uint32_t pack_bf16x2(__nv_bfloat16 a, __nv_bfloat16 b) {
    uint16_t ua = __bfloat16_as_ushort(a);
    uint16_t ub = __bfloat16_as_ushort(b);
    return (uint32_t)ua | ((uint32_t)ub << 16);
}

// rounded hi/lo split of two floats -> packed bf16x2 words
__device__ __forceinline__ void split2(float x, float y, uint32_t& hw, uint32_t& lw) {
    __nv_bfloat16 h0 = __float2bfloat16_rn(x);
    __nv_bfloat16 h1 = __float2bfloat16_rn(y);
    __nv_bfloat16 l0 = __float2bfloat16_rn(x - __bfloat162float(h0));
    __nv_bfloat16 l1 = __float2bfloat16_rn(y - __bfloat162float(h1));
    hw = pack_bf16x2(h0, h1);
    lw = pack_bf16x2(l0, l1);
}

// truncation hi/lo split (cheaper; lo = x - hi is EXACT):
// hw = {hi16(y), hi16(x)}, lo captured by rounded cvt of exact remainder.
__device__ __forceinline__ void tsplit2(float x, float y, uint32_t& hw, uint32_t& lw) {
    uint32_t bx = __float_as_uint(x), by = __float_as_uint(y);
    uint32_t hx = bx & 0xFFFF0000u,   hy = by & 0xFFFF0000u;
    hw = (hx >> 16) | hy;                         // PRMT-able pack
    float l0 = x - __uint_as_float(hx);
    float l1 = y - __uint_as_float(hy);
    lw = pack_bf16x2(__float2bfloat16_rn(l0), __float2bfloat16_rn(l1));
}

__device__ __forceinline__ void split1(float x, __nv_bfloat16& h, __nv_bfloat16& l) {
    h = __float2bfloat16_rn(x);
    l = __float2bfloat16_rn(x - __bfloat162float(h));
}

#if TC_OK
__device__ __forceinline__ uint32_t elect_one_pred() {
    uint32_t pred;
    asm volatile("{\n\t.reg .pred p;\n\telect.sync _|p, 0xFFFFFFFF;\n\t"
                 "selp.b32 %0, 1, 0, p;\n\t}" : "=r"(pred));
    return pred;
}
#define MBARRIER_INIT(addr, cnt) \
    asm volatile("mbarrier.init.shared.b64 [%0], %1;" :: "r"((uint32_t)(addr)), "r"((uint32_t)(cnt)) : "memory")
#define MBARRIER_INVAL(addr) \
    asm volatile("mbarrier.inval.shared.b64 [%0];" :: "r"((uint32_t)(addr)) : "memory")
#define MBARRIER_WAIT_PARITY(mbar_smem_addr, phase_parity) do { \
    uint32_t _mbar = (uint32_t)(mbar_smem_addr); \
    uint32_t _parity = (uint32_t)(phase_parity); \
    uint32_t _done; \
    asm volatile("{\n\t.reg .pred p;\n\t" \
        "mbarrier.try_wait.parity.acquire.cta.shared::cta.b64 p, [%1], %2;\n\t" \
        "selp.b32 %0, 1, 0, p;\n\t}" \
        : "=r"(_done) : "r"(_mbar), "r"(_parity) : "memory"); \
    if (!_done) { \
        asm volatile("{\n\t.reg .pred P1;\n\t" \
            "WAIT_LOOP_%=:\n\t" \
            "mbarrier.try_wait.parity.acquire.cta.shared::cta.b64 P1, [%0], %1, 0x989680;\n\t" \
            "@P1 bra.uni WAIT_DONE_%=;\n\t" \
            "bra.uni WAIT_LOOP_%=;\n\t" \
            "WAIT_DONE_%=:\n\t}" \
            :: "r"(_mbar), "r"(_parity) : "memory"); \
    } \
} while(0)
#define TCGEN05_ALLOC(smem_result_addr, nCols) \
    asm volatile("tcgen05.alloc.cta_group::1.sync.aligned.shared::cta.b32 [%0], %1;" \
        :: "r"((uint32_t)(smem_result_addr)), "r"((uint32_t)(nCols)) : "memory")
#define TCGEN05_DEALLOC(tmem_addr, nCols) \
    asm volatile("tcgen05.dealloc.cta_group::1.sync.aligned.b32 %0, %1;" \
        :: "r"(tmem_addr), "r"((uint32_t)(nCols)))
#define TCGEN05_RELINQUISH() \
    asm volatile("tcgen05.relinquish_alloc_permit.cta_group::1.sync.aligned;")
#define TCGEN05_COMMIT(mbar_smem_addr) \
    asm volatile("tcgen05.commit.cta_group::1.mbarrier::arrive::one.shared::cluster.b64 [%0];" \
        :: "r"((uint32_t)(mbar_smem_addr)) : "memory")
#define TCGEN05_FENCE_BEFORE() \
    asm volatile("tcgen05.fence::before_thread_sync;" ::: "memory")
#define TCGEN05_FENCE_AFTER() \
    asm volatile("tcgen05.fence::after_thread_sync;" ::: "memory")
#define TCGEN05_WAIT_LD() \
    asm volatile("tcgen05.wait::ld.sync.aligned;" ::: "memory")
#define TCGEN05_WAIT_ST() \
    asm volatile("tcgen05.wait::st.sync.aligned;" ::: "memory")
#define TCGEN05_LD_32X32B_X32(r, tmem_addr) \
    asm volatile("tcgen05.ld.sync.aligned.32x32b.x32.b32 " \
        "{%0, %1, %2, %3, %4, %5, %6, %7, " \
        " %8, %9, %10, %11, %12, %13, %14, %15, " \
        " %16, %17, %18, %19, %20, %21, %22, %23, " \
        " %24, %25, %26, %27, %28, %29, %30, %31}, [%32];" \
        : "=r"((r)[0]),  "=r"((r)[1]),  "=r"((r)[2]),  "=r"((r)[3]), \
          "=r"((r)[4]),  "=r"((r)[5]),  "=r"((r)[6]),  "=r"((r)[7]), \
          "=r"((r)[8]),  "=r"((r)[9]),  "=r"((r)[10]), "=r"((r)[11]), \
          "=r"((r)[12]), "=r"((r)[13]), "=r"((r)[14]), "=r"((r)[15]), \
          "=r"((r)[16]), "=r"((r)[17]), "=r"((r)[18]), "=r"((r)[19]), \
          "=r"((r)[20]), "=r"((r)[21]), "=r"((r)[22]), "=r"((r)[23]), \
          "=r"((r)[24]), "=r"((r)[25]), "=r"((r)[26]), "=r"((r)[27]), \
          "=r"((r)[28]), "=r"((r)[29]), "=r"((r)[30]), "=r"((r)[31]) \
        : "r"(tmem_addr))
#define TCGEN05_LD_32X32B_X8(r, tmem_addr) \
    asm volatile("tcgen05.ld.sync.aligned.32x32b.x8.b32 " \
        "{%0, %1, %2, %3, %4, %5, %6, %7}, [%8];" \
        : "=r"((r)[0]), "=r"((r)[1]), "=r"((r)[2]), "=r"((r)[3]), \
          "=r"((r)[4]), "=r"((r)[5]), "=r"((r)[6]), "=r"((r)[7]) \
        : "r"(tmem_addr))
#define TCGEN05_ST_32X32B_X16(tmem_addr, r) \
    asm volatile("tcgen05.st.sync.aligned.32x32b.x16.b32 [%0], " \
        "{%1, %2, %3, %4, %5, %6, %7, %8, " \
        " %9, %10, %11, %12, %13, %14, %15, %16};" \
        :: "r"(tmem_addr), \
           "r"((r)[0]),  "r"((r)[1]),  "r"((r)[2]),  "r"((r)[3]), \
           "r"((r)[4]),  "r"((r)[5]),  "r"((r)[6]),  "r"((r)[7]), \
           "r"((r)[8]),  "r"((r)[9]),  "r"((r)[10]), "r"((r)[11]), \
           "r"((r)[12]), "r"((r)[13]), "r"((r)[14]), "r"((r)[15]) \
        : "memory")

static constexpr uint64_t SMEM_DESC_BASE_SW128 =
    (uint64_t(2)  << 61) | (uint64_t(1) << 46) | (uint64_t(64) << 32) | (uint64_t(1) << 16);
#define MAKE_SMEM_DESC(base_addr) \
    (SMEM_DESC_BASE_SW128 | ((uint64_t)((base_addr) >> 4) & 0x3FFF))

__device__ __forceinline__ void mma_bf16_ss(uint32_t d, uint64_t ad, uint64_t bd,
                                            uint32_t idesc, uint32_t enable) {
    asm volatile(
        "{\n\t.reg .pred p;\n\tsetp.ne.u32 p, %4, 0;\n\t"
        "tcgen05.mma.cta_group::1.kind::f16 [%0], %1, %2, %3, {%5, %5, %5, %5}, p;\n\t}"
        :: "r"(d), "l"(ad), "l"(bd), "r"(idesc), "r"(enable), "r"(0u)
        : "memory");
}
__device__ __forceinline__ void mma_bf16_ts(uint32_t d, uint32_t a, uint64_t bd,
                                            uint32_t idesc, uint32_t enable) {
    asm volatile(
        "{\n\t.reg .pred p;\n\tsetp.ne.u32 p, %4, 0;\n\t"
        "tcgen05.mma.cta_group::1.kind::f16 [%0], [%1], %2, %3, {%5, %5, %5, %5}, p;\n\t}"
        :: "r"(d), "r"(a), "l"(bd), "r"(idesc), "r"(enable), "r"(0u)
        : "memory");
}

__device__ __forceinline__ uint32_t kmaj_off(int row, int col, int natr) {
    int ac = col >> 6, ic = col & 63;
    int ar = row >> 3, ir = row & 7;
    uint32_t off = (uint32_t)((ar + ac * natr) * 1024 + ir * 128 + ic * 2);
    return off ^ ((off >> 3) & 0x70);
}
#endif // TC_OK

// ---------------------------------------------------------------------------
// one-shot fp32 -> bf16 hi/lo split for hidden, qkv_w, proj_w
// ---------------------------------------------------------------------------
__global__ __launch_bounds__(256) void split_all_kernel(
    const float* __restrict__ hidden, const float* __restrict__ qkv_w,
    const float* __restrict__ proj_w)
{
    const int nA4 = (S_TOT * E_DIM) / 4;
    const int nB4 = (QKV_N * E_DIM) / 4;
    const int nP4 = (E_DIM * E_DIM) / 4;
    int i4 = blockIdx.x * blockDim.x + threadIdx.x;
    const float* src;
    __nv_bfloat16 *hi, *lo;
    size_t o4;
    if (i4 < nA4) {
        src = hidden; hi = g_Ah; lo = g_Al; o4 = i4;
    } else if (i4 < nA4 + nB4) {
        src = qkv_w; hi = g_Bh; lo = g_Bl; o4 = i4 - nA4;
    } else if (i4 < nA4 + nB4 + nP4) {
        src = proj_w; hi = g_Ph; lo = g_Pl; o4 = i4 - nA4 - nB4;
    } else return;
    float4 v = *(const float4*)(src + o4 * 4);
    uint32_t h01, l01, h23, l23;
    split2(v.x, v.y, h01, l01);
    split2(v.z, v.w, h23, l23);
    *(uint2*)(hi + o4 * 4) = make_uint2(h01, h23);
    *(uint2*)(lo + o4 * 4) = make_uint2(l01, l23);
}

// ---------------------------------------------------------------------------
// tcgen05 GEMM (R13 double-buffered version — best measured).
// 256x128 tile, cp.async, KC=64 x2 buffers. bsel: 0=g_B*, 1=g_P*
// ---------------------------------------------------------------------------
#define KC 64
#define TILE_B 16384
#define STAGE_B (6 * TILE_B)
#define GEMM_SMEM (1024 + 2 * STAGE_B)

#if TC_OK
__device__ __forceinline__ void cp_tile(uint32_t sdst,
                                        const __nv_bfloat16* __restrict__ gsrc,
                                        int row0, int k0, int K, int tid) {
    #pragma unroll
    for (int it = 0; it < 4; it++) {
        int idx = tid + it * 256;
        int rr = idx >> 3, c = idx & 7;
        const void* src = gsrc + (size_t)(row0 + rr) * K + k0 + c * 8;
        uint32_t off = (uint32_t)((rr << 7) | (c << 4));
        uint32_t sw = off ^ ((off >> 3) & 0x70);
        asm volatile("cp.async.cg.shared.global [%0], [%1], 16;"
            :: "r"(sdst + sw), "l"(src) : "memory");
    }
}
__device__ __forceinline__ void cp_stage(uint32_t base, int row0, int col0,
                                         int k0, int K, int tid,
                                         const __nv_bfloat16* Bh,
                                         const __nv_bfloat16* Bl) {
    cp_tile(base,              g_Ah, row0,       k0, K, tid);
    cp_tile(base + TILE_B,     g_Al, row0,       k0, K, tid);
    cp_tile(base + 2 * TILE_B, g_Ah, row0 + 128, k0, K, tid);
    cp_tile(base + 3 * TILE_B, g_Al, row0 + 128, k0, K, tid);
    cp_tile(base + 4 * TILE_B, Bh,   col0,       k0, K, tid);
    cp_tile(base + 5 * TILE_B, Bl,   col0,       k0, K, tid);
    asm volatile("cp.async.commit_group;" ::: "memory");
}
__device__ __forceinline__ void issue_chunk2(uint32_t base, uint32_t tmem,
                                             uint32_t idesc, uint32_t mbar, int first) {
    asm volatile("fence.proxy.async.shared::cta;" ::: "memory");
    uint64_t dAh0 = MAKE_SMEM_DESC(base);
    uint64_t dAl0 = MAKE_SMEM_DESC(base + TILE_B);
    uint64_t dAh1 = MAKE_SMEM_DESC(base + 2 * TILE_B);
    uint64_t dAl1 = MAKE_SMEM_DESC(base + 3 * TILE_B);
    uint64_t dBh  = MAKE_SMEM_DESC(base + 4 * TILE_B);
    uint64_t dBl  = MAKE_SMEM_DESC(base + 5 * TILE_B);
    #pragma unroll
    for (int ks = 0; ks < 4; ks++) {
        uint32_t en = (first && ks == 0) ? 0u : 1u;
        mma_bf16_ss(tmem,       dAh0 + ks * 2, dBh + ks * 2, idesc, en);
        mma_bf16_ss(tmem,       dAh0 + ks * 2, dBl + ks * 2, idesc, 1u);
        mma_bf16_ss(tmem,       dAl0 + ks * 2, dBh + ks * 2, idesc, 1u);
        mma_bf16_ss(tmem + 128, dAh1 + ks * 2, dBh + ks * 2, idesc, en);
        mma_bf16_ss(tmem + 128, dAh1 + ks * 2, dBl + ks * 2, idesc, 1u);
        mma_bf16_ss(tmem + 128, dAl1 + ks * 2, dBh + ks * 2, idesc, 1u);
    }
    TCGEN05_COMMIT(mbar);
}
#endif

__global__ __launch_bounds__(256) void gemm_tc(
    const float* __restrict__ bias, float* __restrict__ Cext,
    int M, int N, int K, int mode, int bsel)
{
    extern __shared__ char smem[];
    const int tid = threadIdx.x;
    float* C = mode ? Cext : g_qkv;
    const __nv_bfloat16* Bh = bsel ? g_Ph : g_Bh;
    const __nv_bfloat16* Bl = bsel ? g_Pl : g_Bl;

#if TC_OK
    uint32_t sb = smem_to_u32(smem);
    const int wid = tid >> 5;

    if (wid == 0) {
        TCGEN05_ALLOC(sb, 256);
        TCGEN05_RELINQUISH();
    }
    if (tid == 0) {
        MBARRIER_INIT(sb + 8, 1);
        MBARRIER_INIT(sb + 16, 1);
    }
    __syncthreads();
    uint32_t tmem;
    asm volatile("ld.shared.b32 %0, [%1];" : "=r"(tmem) : "r"(sb));

    const int row0 = blockIdx.y * 256;
    const int col0 = blockIdx.x * 128;
    const int NC = K / KC;
    const uint32_t idesc = 0x490u | ((128u / 8) << 17) | ((128u / 16) << 24);

    cp_stage(sb + 1024, row0, col0, 0, K, tid, Bh, Bl);
    if (NC > 1)
        cp_stage(sb + 1024 + STAGE_B, row0, col0, KC, K, tid, Bh, Bl);

    int ph0 = 0, ph1 = 0;
    for (int c = 0; c < NC; c++) {
        const int buf = c & 1;
        uint32_t base = sb + 1024 + buf * STAGE_B;
        if (c + 1 < NC) asm volatile("cp.async.wait_group 1;" ::: "memory");
        else            asm volatile("cp.async.wait_group 0;" ::: "memory");
        __syncthreads();
        if (tid < 32 && elect_one_pred())
            issue_chunk2(base, tmem, idesc, sb + 8 + buf * 8, c == 0);
        if (c + 2 < NC) {
            if (buf == 0) { MBARRIER_WAIT_PARITY(sb + 8, ph0);  ph0 ^= 1; }
            else          { MBARRIER_WAIT_PARITY(sb + 16, ph1); ph1 ^= 1; }
            cp_stage(base, row0, col0, (c + 2) * KC, K, tid, Bh, Bl);
        }
    }

    MBARRIER_WAIT_PARITY(sb + 8,  ph0);
    MBARRIER_WAIT_PARITY(sb + 16, ph1);
    TCGEN05_FENCE_AFTER();

    {
        const int lane = tid & 31;
        const int sub = wid & 3;
        const int grp = wid >> 2;
        const int r = row0 + grp * 128 + sub * 32 + lane;
        const uint32_t tm = tmem + grp * 128;
        #pragma unroll
        for (int cc = 0; cc < 4; cc++) {
            uint32_t regs[32];
            TCGEN05_LD_32X32B_X32(regs, tm + cc * 32);
            TCGEN05_WAIT_LD();
            float* crow = C + (size_t)r * N + col0 + cc * 32;
            const float* brow = bias + col0 + cc * 32;
            #pragma unroll
            for (int j = 0; j < 32; j += 4) {
                float4 o;
                o.x = __uint_as_float(regs[j + 0]) + brow[j + 0];
                o.y = __uint_as_float(regs[j + 1]) + brow[j + 1];
                o.z = __uint_as_float(regs[j + 2]) + brow[j + 2];
                o.w = __uint_as_float(regs[j + 3]) + brow[j + 3];
                *(float4*)(crow + j) = o;
            }
        }
    }

    __syncthreads();
    if (tid == 0) { MBARRIER_INVAL(sb + 8); MBARRIER_INVAL(sb + 16); }
    __syncthreads();
    if (wid == 0) TCGEN05_DEALLOC(tmem, 256);

#else
    // fallback: fp32 FFMA tiled GEMM (compile-only for family-PTX pass)
    float* As = (float*)smem;
    float* Bs = (float*)(smem + 8 * 128 * 4);
    const int col0 = blockIdx.x * 128;
    const int lr = tid >> 1;
    const int lc = (tid & 1) * 4;
    const int tx = tid & 15;
    const int ty = tid >> 4;
    for (int half = 0; half < 2; half++) {
        const int row0 = blockIdx.y * 256 + half * 128;
        float acc[8][8];
        for (int i = 0; i < 8; i++) for (int j = 0; j < 8; j++) acc[i][j] = 0.f;
        for (int k0 = 0; k0 < K; k0 += 8) {
            for (int u = 0; u < 4; u++) {
                size_t ai = (size_t)(row0 + lr) * K + k0 + lc + u;
                size_t bi = (size_t)(col0 + lr) * K + k0 + lc + u;
                As[(lc + u) * 128 + lr] = __bfloat162float(g_Ah[ai]) + __bfloat162float(g_Al[ai]);
                Bs[(lc + u) * 128 + lr] = __bfloat162float(Bh[bi]) + __bfloat162float(Bl[bi]);
            }
            __syncthreads();
            for (int k = 0; k < 8; k++)
                for (int i = 0; i < 8; i++)
                    for (int j = 0; j < 8; j++)
                        acc[i][j] = fmaf(As[k * 128 + ty * 8 + i], Bs[k * 128 + tx * 8 + j], acc[i][j]);
            __syncthreads();
        }
        for (int i = 0; i < 8; i++) {
            size_t r = (size_t)(row0 + ty * 8 + i);
            for (int j = 0; j < 8; j++) {
                int cidx = col0 + tx * 8 + j;
                C[r * N + cidx] = acc[i][j] + bias[cidx];
            }
        }
        __syncthreads();
    }
#endif
}

// ---------------------------------------------------------------------------
// merged RoPE + V-transpose kernel.
// ---------------------------------------------------------------------------
#define ROPE_BLOCKS ((S_TOT * H_NUM * 36) / 256)    // 9216

__global__ __launch_bounds__(256) void ropevt_kernel(
    const float* __restrict__ cosv, const float* __restrict__ sinv, int L)
{
    __shared__ float vs[64][73];
    const int tid = threadIdx.x;

    if (blockIdx.x < ROPE_BLOCKS) {
        const float SCALE = 0.11785113019775793f;
        int idx = blockIdx.x * 256 + tid;
        int d = idx % 36;
        int h = (idx / 36) % H_NUM;
        int s = idx / (36 * H_NUM);

        float c1 = cosv[s * D_DIM + d],      s1 = sinv[s * D_DIM + d];
        float c2 = cosv[s * D_DIM + d + 36], s2 = sinv[s * D_DIM + d + 36];

        int b = s / L, m = s - b * L;
        size_t obase = ((size_t)(b * H_NUM + h) * L + m) * 72;

        size_t base = (size_t)s * QKV_N + h * D_DIM;
        float x1 = g_qkv[base + d], x2 = g_qkv[base + d + 36];
        float q1 = (x1 * c1 - x2 * s1) * SCALE;
        float q2 = (x2 * c2 + x1 * s2) * SCALE;
        __nv_bfloat16 hh, ll;
        split1(q1, hh, ll); g_Qh[obase + d] = hh;      g_Ql[obase + d] = ll;
        split1(q2, hh, ll); g_Qh[obase + d + 36] = hh; g_Ql[obase + d + 36] = ll;

        base += E_DIM;
        x1 = g_qkv[base + d]; x2 = g_qkv[base + d + 36];
        float k1 = x1 * c1 - x2 * s1;
        float k2 = x2 * c2 + x1 * s2;
        split1(k1, hh, ll); g_Kh[obase + d] = hh;      g_Kl[obase + d] = ll;
        split1(k2, hh, ll); g_Kh[obase + d + 36] = hh; g_Kl[obase + d + 36] = ll;
    } else {
        int bid = blockIdx.x - ROPE_BLOCKS;
        const int ntk = L / 64;
        const int bh = bid / ntk;
        const int k0 = (bid - bh * ntk) * 64;
        const int b = bh / H_NUM, h = bh % H_NUM;

        for (int idx = tid; idx < 64 * 72; idx += 256) {
            int r = idx / 72, d = idx % 72;
            vs[r][d] = g_qkv[(size_t)(b * L + k0 + r) * QKV_N + 2 * E_DIM + h * D_DIM + d];
        }
        __syncthreads();
        for (int idx = tid; idx < 72 * 32; idx += 256) {
            int d = idx >> 5, k2 = (idx & 31) * 2;
            uint32_t hw, lw;
            split2(vs[k2][d], vs[k2 + 1][d], hw, lw);
            size_t o = ((size_t)bh * 72 + d) * L + k0 + k2;
            *(uint32_t*)&g_Vth[o] = hw;
            *(uint32_t*)&g_Vtl[o] = lw;
        }
    }
}

// ---------------------------------------------------------------------------
// Fused flash attention v7b: R13 structure, truncation split in the hot loop.
// SMEM: ctrl 0..63 | rowsum[4][128] 64..2112 | QH 4096 | QL 36864 |
//       KH 69632 | KL 102400 | V0H 135168 | V0L 153600 | V1H 172032 |
//       V1L 190464 | end 208896
// TMEM: O 0..71 | S0 128..255 | S1 256..383 | Ph 384..447 | Pl 448..511
// ---------------------------------------------------------------------------
#define AT7_QH 4096
#define AT7_QL 36864
#define AT7_KH 69632
#define AT7_KL 102400
#define AT7_V0H 135168
#define AT7_V0L 153600
#define AT7_V1H 172032
#define AT7_V1L 190464
#define AT7_SMEM 208896

#if TC_OK
__device__ __forceinline__ void cp_att_k(uint32_t sdst,
    const __nv_bfloat16* __restrict__ g, int bh, int k0, int L, int tid)
{
    #pragma unroll
    for (int it = 0; it < 3; it++) {
        int idx = tid + it * 512;
        if (idx < 1152) {
            int r = idx / 9, c = idx - r * 9;
            const void* src = g + ((size_t)bh * L + k0 + r) * 72 + c * 8;
            uint32_t off = kmaj_off(r, c * 8, 16);
            asm volatile("cp.async.cg.shared.global [%0], [%1], 16;"
                :: "r"(sdst + off), "l"(src) : "memory");
        }
    }
}
__device__ __forceinline__ void cp_att_v(uint32_t sdst,
    const __nv_bfloat16* __restrict__ g, int bh, int k0, int L, int tid)
{
    #pragma unroll
    for (int it = 0; it < 3; it++) {
        int idx = tid + it * 512;
        if (idx < 1152) {
            int d = idx >> 4, c = idx & 15;
            const void* src = g + ((size_t)bh * 72 + d) * L + k0 + c * 8;
            uint32_t off = kmaj_off(d, c * 8, 9);
            asm volatile("cp.async.cg.shared.global [%0], [%1], 16;"
                :: "r"(sdst + off), "l"(src) : "memory");
        }
    }
}
__device__ __forceinline__ void issue_s(uint32_t tmem_S, uint32_t sb,
                                        uint32_t idesc_s, uint32_t mbar) {
    const int qk_off[5] = {0, 2, 4, 6, 1024};
    uint64_t dQH = MAKE_SMEM_DESC(sb + AT7_QH);
    uint64_t dQL = MAKE_SMEM_DESC(sb + AT7_QL);
    uint64_t dKH = MAKE_SMEM_DESC(sb + AT7_KH);
    uint64_t dKL = MAKE_SMEM_DESC(sb + AT7_KL);
    #pragma unroll
    for (int ks = 0; ks < 5; ks++) {
        mma_bf16_ss(tmem_S, dQH + qk_off[ks], dKH + qk_off[ks], idesc_s, ks > 0);
        mma_bf16_ss(tmem_S, dQH + qk_off[ks], dKL + qk_off[ks], idesc_s, 1u);
        mma_bf16_ss(tmem_S, dQL + qk_off[ks], dKH + qk_off[ks], idesc_s, 1u);
    }
    TCGEN05_COMMIT(mbar);
}
__device__ __forceinline__ void issue_pv(uint32_t tmem_O, uint32_t tmem_Ph,
                                         uint32_t tmem_Pl, uint32_t vbase,
                                         uint32_t idesc_o, uint32_t mbar, int first) {
    const int v_off[8] = {0, 2, 4, 6, 576, 578, 580, 582};
    uint64_t dVH = MAKE_SMEM_DESC(vbase);
    uint64_t dVL = MAKE_SMEM_DESC(vbase + (AT7_V0L - AT7_V0H));
    #pragma unroll
    for (int ks = 0; ks < 8; ks++) {
        mma_bf16_ts(tmem_O, tmem_Ph + ks * 8, dVH + v_off[ks], idesc_o,
                    (first && ks == 0) ? 0u : 1u);
        mma_bf16_ts(tmem_O, tmem_Ph + ks * 8, dVL + v_off[ks], idesc_o, 1u);
        mma_bf16_ts(tmem_O, tmem_Pl + ks * 8, dVH + v_off[ks], idesc_o, 1u);
    }
    TCGEN05_COMMIT(mbar);
}
#endif

__global__ __launch_bounds__(512, 1) void fused_attn_kernel(int L)
{
    extern __shared__ char smem[];
    const int tid = threadIdx.x;
    const int bh = blockIdx.y;
    const int m0 = blockIdx.x * 128;
    const int nkt = L / 128;

#if TC_OK
    uint32_t sb = smem_to_u32(smem);
    const int wid = tid >> 5;
    const int lane = tid & 31;

    if (wid == 0) {
        TCGEN05_ALLOC(sb, 512);
        TCGEN05_RELINQUISH();
    }
    if (tid == 0) {
        MBARRIER_INIT(sb + 8, 1);    // mb_s  (S MMA completion)
        MBARRIER_INIT(sb + 16, 1);   // mb_pv (PV MMA completion)
    }
    __syncthreads();
    uint32_t tmem;
    asm volatile("ld.shared.b32 %0, [%1];" : "=r"(tmem) : "r"(sb));
    const uint32_t tmem_O  = tmem;
    const uint32_t tmem_Ph = tmem + 384;
    const uint32_t tmem_Pl = tmem + 448;

    const uint32_t idesc_s = 0x490u | (16u << 17) | (8u << 24);  // N=128
    const uint32_t idesc_o = 0x490u | (9u  << 17) | (8u << 24);  // N=72

    // prologue: load Q + K(0) (group A), V(0) (group B)
    cp_att_k(sb + AT7_QH, g_Qh, bh, m0, L, tid);
    cp_att_k(sb + AT7_QL, g_Ql, bh, m0, L, tid);
    cp_att_k(sb + AT7_KH, g_Kh, bh, 0, L, tid);
    cp_att_k(sb + AT7_KL, g_Kl, bh, 0, L, tid);
    asm volatile("cp.async.commit_group;" ::: "memory");
    cp_att_v(sb + AT7_V0H, g_Vth, bh, 0, L, tid);
    cp_att_v(sb + AT7_V0L, g_Vtl, bh, 0, L, tid);
    asm volatile("cp.async.commit_group;" ::: "memory");

    // zero pad cols 72..79 of QH, QL, KH, KL
    {
        int bf = tid >> 7, r = tid & 127;
        uint32_t bases[4] = {AT7_QH, AT7_QL, AT7_KH, AT7_KL};
        uint32_t dst = sb + bases[bf] + kmaj_off(r, 72, 16);
        asm volatile("st.shared.v4.b32 [%0], {%1,%1,%1,%1};"
            :: "r"(dst), "r"(0u) : "memory");
    }

    // Q + K(0) ready -> issue S(0)
    asm volatile("cp.async.wait_group 1;" ::: "memory");
    __syncthreads();
    if (tid < 32 && elect_one_pred()) {
        asm volatile("fence.proxy.async.shared::cta;" ::: "memory");
        TCGEN05_FENCE_AFTER();
        issue_s(tmem + 128, sb, idesc_s, sb + 8);
    }
    MBARRIER_WAIT_PARITY(sb + 8, 0);
    int ph_s = 1;
    if (nkt > 1) {
        cp_att_k(sb + AT7_KH, g_Kh, bh, 128, L, tid);
        cp_att_k(sb + AT7_KL, g_Kl, bh, 128, L, tid);
        asm volatile("cp.async.commit_group;" ::: "memory");
    }

    const int sub = wid & 3;
    const int grp = wid >> 2;
    const int row = sub * 32 + lane;
    const int c0 = grp * 32;
    const uint32_t woff = (uint32_t)sub << 21;
    float psum = 0.f;
    int ph_pv = 0;

    for (int kt = 0; kt < nkt; kt++) {
        const uint32_t tmem_S = tmem + 128 + (kt & 1) * 128;

        asm volatile("cp.async.wait_group 0;" ::: "memory");
        __syncthreads();
        if (kt + 1 < nkt) {
            if (tid < 32 && elect_one_pred()) {
                asm volatile("fence.proxy.async.shared::cta;" ::: "memory");
                TCGEN05_FENCE_AFTER();
                issue_s(tmem + 128 + ((kt + 1) & 1) * 128, sb, idesc_s, sb + 8);
            }
        }
        TCGEN05_FENCE_AFTER();

        // softmax: read S(kt), exp, psum, truncation-split into P regs
        uint32_t r32[32];
        TCGEN05_LD_32X32B_X32(r32, tmem_S + c0);
        TCGEN05_WAIT_LD();
        uint32_t ph16[16], pl16[16];
        #pragma unroll
        for (int j = 0; j < 16; j++) {
            float e0 = __expf(__uint_as_float(r32[2 * j]));
            float e1 = __expf(__uint_as_float(r32[2 * j + 1]));
            psum += e0 + e1;
            tsplit2(e0, e1, ph16[j], pl16[j]);
        }

        if (kt >= 1) {
            MBARRIER_WAIT_PARITY(sb + 16, ph_pv);
            ph_pv ^= 1;
        }
        TCGEN05_FENCE_AFTER();

        TCGEN05_ST_32X32B_X16(tmem_Ph + grp * 16 + woff, ph16);
        TCGEN05_ST_32X32B_X16(tmem_Pl + grp * 16 + woff, pl16);
        TCGEN05_WAIT_ST();
        TCGEN05_FENCE_BEFORE();

        if (kt + 1 < nkt) {
            MBARRIER_WAIT_PARITY(sb + 8, ph_s);
            ph_s ^= 1;
            if (kt + 2 < nkt) {
                cp_att_k(sb + AT7_KH, g_Kh, bh, (kt + 2) * 128, L, tid);
                cp_att_k(sb + AT7_KL, g_Kl, bh, (kt + 2) * 128, L, tid);
            }
            uint32_t vb = sb + ((kt + 1) & 1 ? AT7_V1H : AT7_V0H);
            cp_att_v(vb,                       g_Vth, bh, (kt + 1) * 128, L, tid);
            cp_att_v(vb + (AT7_V0L - AT7_V0H), g_Vtl, bh, (kt + 1) * 128, L, tid);
            asm volatile("cp.async.commit_group;" ::: "memory");
        }
        __syncthreads();

        if (tid < 32 && elect_one_pred()) {
            asm volatile("fence.proxy.async.shared::cta;" ::: "memory");
            TCGEN05_FENCE_AFTER();
            uint32_t vbase = sb + ((kt & 1) ? AT7_V1H : AT7_V0H);
            issue_pv(tmem_O, tmem_Ph, tmem_Pl, vbase, idesc_o, sb + 16, kt == 0);
        }
    }

    MBARRIER_WAIT_PARITY(sb + 16, ph_pv);
    TCGEN05_FENCE_AFTER();

    *(float*)(smem + 64 + (grp * 128 + row) * 4) = psum;
    __syncthreads();

    if (wid < 4) {
        float rs = *(float*)(smem + 64 + row * 4) +
                   *(float*)(smem + 64 + (128 + row) * 4) +
                   *(float*)(smem + 64 + (256 + row) * 4) +
                   *(float*)(smem + 64 + (384 + row) * 4);
        float inv = 1.f / rs;
        uint32_t r32[72];
        TCGEN05_LD_32X32B_X32(r32,      tmem_O);
        TCGEN05_LD_32X32B_X32(r32 + 32, tmem_O + 32);
        TCGEN05_LD_32X32B_X8 (r32 + 64, tmem_O + 64);
        TCGEN05_WAIT_LD();
        const int b = bh / H_NUM, h = bh % H_NUM;
        size_t obase = (size_t)(b * L + m0 + row) * E_DIM + h * D_DIM;
        #pragma unroll
        for (int j = 0; j < 72; j += 2) {
            float o0 = __uint_as_float(r32[j]) * inv;
            float o1 = __uint_as_float(r32[j + 1]) * inv;
            uint32_t hw, lw;
            tsplit2(o0, o1, hw, lw);
            *(uint32_t*)&g_Ah[obase + j] = hw;
            *(uint32_t*)&g_Al[obase + j] = lw;
        }
    }

    __syncthreads();
    if (tid == 0) {
        MBARRIER_INVAL(sb + 8);
        MBARRIER_INVAL(sb + 16);
    }
    __syncthreads();
    if (wid == 0) TCGEN05_DEALLOC(tmem, 512);

#else
    // naive fallback (compile-only for the family-PTX pass); reads split Q/K
    const int b = bh / H_NUM, h = bh % H_NUM;
    const int row = tid >> 2;
    const int hf = tid & 3;
    if (row < 128 && hf < 2) {
        float q[D_DIM];
        size_t qbase = ((size_t)bh * L + m0 + row) * 72;
        for (int d = 0; d < D_DIM; d++)
            q[d] = __bfloat162float(g_Qh[qbase + d]) + __bfloat162float(g_Ql[qbase + d]);
        float o[36];
        for (int j = 0; j < 36; j++) o[j] = 0.f;
        float rsum = 0.f;
        for (int k = 0; k < L; k++) {
            size_t kbase = ((size_t)bh * L + k) * 72;
            float s = 0.f;
            for (int d = 0; d < D_DIM; d++)
                s += q[d] * (__bfloat162float(g_Kh[kbase + d]) + __bfloat162float(g_Kl[kbase + d]));
            float e = __expf(s);
            rsum += e;
            const float* vv = &g_qkv[(size_t)(b * L + k) * QKV_N + 2 * E_DIM + h * D_DIM + hf * 36];
            for (int j = 0; j < 36; j++) o[j] += e * vv[j];
        }
        float inv = 1.f / rsum;
        size_t obase = (size_t)(b * L + m0 + row) * E_DIM + h * D_DIM + hf * 36;
        for (int j = 0; j < 36; j++) {
            float val = o[j] * inv;
            __nv_bfloat16 hi = __float2bfloat16_rn(val);
            __nv_bfloat16 lo = __float2bfloat16_rn(val - __bfloat162float(hi));
            g_Ah[obase + j] = hi;
            g_Al[obase + j] = lo;
        }
    }
#endif
}

// ---------------------------------------------------------------------------
extern "C" void kernel_launch(void* const* d_in, const int* in_sizes, int n_in,
                              void* d_out, int out_size)
{
    const float* hidden = (const float*)d_in[0];
    const float* cosv   = (const float*)d_in[1];
    const float* sinv   = (const float*)d_in[2];
    const float* qkv_w  = (const float*)d_in[3];
    const float* qkv_b  = (const float*)d_in[4];
    const float* proj_w = (const float*)d_in[5];
    const float* proj_b = (const float*)d_in[6];

    const int S = S_TOT;
    const int n_chunks = in_sizes[7] - 1;
    const int L = S / n_chunks;
    const int nbh = n_chunks * H_NUM;

    cudaFuncSetAttribute(gemm_tc,
        cudaFuncAttributeMaxDynamicSharedMemorySize, GEMM_SMEM);
    cudaFuncSetAttribute(fused_attn_kernel,
        cudaFuncAttributeMaxDynamicSharedMemorySize, AT7_SMEM);

    // 1) split hidden + qkv_w + proj_w (one launch)
    {
        int total4 = (S * E_DIM + QKV_N * E_DIM + E_DIM * E_DIM) / 4;
        split_all_kernel<<<(total4 + 255) / 256, 256>>>(hidden, qkv_w, proj_w);
    }

    // 2) QKV GEMM (R13 double-buffered)
    gemm_tc<<<dim3(QKV_N / 128, S / 256), 256, GEMM_SMEM>>>(
        qkv_b, nullptr, S, QKV_N, E_DIM, 0, 0);

    // 3) RoPE + V transpose (one launch)
    ropevt_kernel<<<ROPE_BLOCKS + nbh * (L / 64), 256>>>(cosv, sinv, L);

    // 4) fused attention v7b -> g_Ah/g_Al
    fused_attn_kernel<<<dim3(L / 128, nbh), 512, AT7_SMEM>>>(L);

    // 5) proj GEMM
    gemm_tc<<<dim3(E_DIM / 128, S / 256), 256, GEMM_SMEM>>>(
        proj_b, (float*)d_out, S, E_DIM, E_DIM, 1, 1);
}